// round 8
// baseline (speedup 1.0000x reference)
#include <cuda_runtime.h>
#include <cuda_fp16.h>
#include <cstdint>
#include <math.h>

// Problem constants
#define NB 16
#define NL 2048
#define ND 1024
#define NE 64

// ---------------- scratch (device globals; no runtime allocation) ----------------
__device__ __half g_selh[(size_t)NB * NL * ND]; // sigmoid(x @ Ws^T + bs) fp16
__device__ float g_z   [(size_t)NB * NE * NL];   // attention logits (fp32)
__device__ float g_pa  [(size_t)NB * NE * ND];   // normalized A_fw @ x (tf32-rounded)
__device__ float g_pb  [(size_t)NB * NE * ND];
__device__ float g_ca  [(size_t)NB * NE * ND];   // class_a (tf32-rounded)
__device__ float g_cb  [(size_t)NB * NE * ND];   // class_b (tf32-rounded)
__device__ float g_afw [NB * NE];
__device__ float g_bfw [NB * NE];
__device__ float g_abw [NB * NL];
__device__ float g_bbw [NB * NL];
__device__ float g_xtf [(size_t)NB * NL * ND];   // x  tf32-rounded
__device__ float g_wtf [(size_t)4 * ND * ND];    // Wk,Wa,Wb,Ws tf32-rounded
__device__ float g_qtf [(size_t)NE * ND];        // q_emb tf32-rounded
__device__ float g_qw  [(size_t)NE * ND];        // q_emb @ Wk (tf32-rounded)
__device__ float g_qb  [NE];                     // q_emb . bk

// ============================================================================
// helpers
// ============================================================================
__device__ __forceinline__ uint32_t smem_u32(const void* p) {
    uint32_t a;
    asm("{ .reg .u64 t; cvta.to.shared.u64 t, %1; cvt.u32.u64 %0, t; }"
        : "=r"(a) : "l"(p));
    return a;
}

__device__ __forceinline__ void cp_async16(uint32_t dst, const void* src) {
    asm volatile("cp.async.cg.shared.global [%0], [%1], 16;" :: "r"(dst), "l"(src));
}

__device__ __forceinline__ uint32_t cvt_tf32(float v) {
    uint32_t r;
    asm("cvt.rna.tf32.f32 %0, %1;" : "=r"(r) : "f"(v));
    return r;
}
__device__ __forceinline__ float rnd_tf32(float v) {
    return __uint_as_float(cvt_tf32(v));
}

__device__ __forceinline__ void mma_tf32(float* d, const uint32_t* a, const uint32_t* b) {
    asm volatile(
        "mma.sync.aligned.m16n8k8.row.col.f32.tf32.tf32.f32 "
        "{%0,%1,%2,%3}, {%4,%5,%6,%7}, {%8,%9}, {%0,%1,%2,%3};\n"
        : "+f"(d[0]), "+f"(d[1]), "+f"(d[2]), "+f"(d[3])
        : "r"(a[0]), "r"(a[1]), "r"(a[2]), "r"(a[3]), "r"(b[0]), "r"(b[1]));
}

// ============================================================================
// Kernel 0: fp32 -> tf32(RNA) conversion prepass
// ============================================================================
__global__ __launch_bounds__(256) void k_cvt(const float* __restrict__ src,
                                             float* __restrict__ dst, int n4)
{
    int i = blockIdx.x * 256 + threadIdx.x;
    if (i >= n4) return;
    float4 v = ((const float4*)src)[i];
    uint4 o;
    o.x = cvt_tf32(v.x); o.y = cvt_tf32(v.y);
    o.z = cvt_tf32(v.z); o.w = cvt_tf32(v.w);
    ((uint4*)dst)[i] = o;
}

// Kernel 0b: 4 weight matrices in one launch (blockIdx.y selects)
__global__ __launch_bounds__(256) void k_cvt4(
    const float* __restrict__ w0, const float* __restrict__ w1,
    const float* __restrict__ w2, const float* __restrict__ w3)
{
    const float* srcs[4] = { w0, w1, w2, w3 };
    const float* src = srcs[blockIdx.y];
    float* dst = g_wtf + (size_t)blockIdx.y * ND * ND;
    int i = blockIdx.x * 256 + threadIdx.x;
    float4 v = ((const float4*)src)[i];
    uint4 o;
    o.x = cvt_tf32(v.x); o.y = cvt_tf32(v.y);
    o.z = cvt_tf32(v.z); o.w = cvt_tf32(v.w);
    ((uint4*)(dst))[i] = o;
}

// ============================================================================
// Kernel A: selector GEMM + sigmoid.  g_selh = sigmoid(x @ Ws^T + bs)  (fp16)
// M=32768,N=1024,K=1024. CTA 128x256, 8 warps 64x64, BK=32, 3-stage ring.
// ============================================================================
#define PADK 36
#define STG_F ((128 + 256) * PADK)
#define GM_SMEM_BYTES (3 * STG_F * 4)

__global__ __launch_bounds__(256, 1) void k_selgemm(const float* __restrict__ bs)
{
    extern __shared__ float sm[];

    const int n0 = blockIdx.x * 256;
    const int m0 = blockIdx.y * 128;
    const float* Wt = g_wtf + (size_t)3 * ND * ND;

    const int tid = threadIdx.x;
    const int wid = tid >> 5, lane = tid & 31;
    const int wm = wid >> 2, wn = wid & 3;
    const int g = lane >> 2, tg = lane & 3;

    const uint32_t sb = smem_u32(sm);

    float acc[4][8][4];
    #pragma unroll
    for (int mt = 0; mt < 4; mt++)
        #pragma unroll
        for (int nt = 0; nt < 8; nt++)
            #pragma unroll
            for (int r = 0; r < 4; r++) acc[mt][nt][r] = 0.f;

    const int ldRow = tid >> 3;
    const int ldSeg = tid & 7;

    auto load_chunk = [&](int kc, int st) {
        const uint32_t s0 = sb + (uint32_t)(st * STG_F) * 4u;
        const uint32_t bB = s0 + (uint32_t)(128 * PADK) * 4u;
        const float* xs = g_xtf + (size_t)m0 * 1024 + kc * 32;
        const float* ws = Wt    + (size_t)n0 * 1024 + kc * 32;
        #pragma unroll
        for (int s = 0; s < 4; ++s) {
            int row = ldRow + s * 32;
            cp_async16(s0 + (uint32_t)(row * PADK + ldSeg * 4) * 4u,
                       xs + (size_t)row * 1024 + ldSeg * 4);
        }
        #pragma unroll
        for (int s = 0; s < 8; ++s) {
            int row = ldRow + s * 32;
            cp_async16(bB + (uint32_t)(row * PADK + ldSeg * 4) * 4u,
                       ws + (size_t)row * 1024 + ldSeg * 4);
        }
        asm volatile("cp.async.commit_group;" ::: "memory");
    };

    load_chunk(0, 0);
    load_chunk(1, 1);

    for (int it = 0; it < 32; ++it) {
        const int st = it % 3;
        if (it < 31) {
            asm volatile("cp.async.wait_group 1;" ::: "memory");
        } else {
            asm volatile("cp.async.wait_group 0;" ::: "memory");
        }
        __syncthreads();

        const float* As = sm + st * STG_F;
        const float* Bs = As + 128 * PADK;

        #pragma unroll
        for (int ks = 0; ks < 4; ++ks) {
            const int kb = ks * 8;
            uint32_t afr[4][4];
            #pragma unroll
            for (int mt = 0; mt < 4; mt++) {
                const float* ap = As + (wm * 64 + mt * 16 + g) * PADK + kb + tg;
                afr[mt][0] = __float_as_uint(ap[0]);
                afr[mt][1] = __float_as_uint(ap[8 * PADK]);
                afr[mt][2] = __float_as_uint(ap[4]);
                afr[mt][3] = __float_as_uint(ap[8 * PADK + 4]);
            }
            uint32_t bfr[8][2];
            #pragma unroll
            for (int nt = 0; nt < 8; nt++) {
                const float* bp = Bs + (wn * 64 + nt * 8 + g) * PADK + kb + tg;
                bfr[nt][0] = __float_as_uint(bp[0]);
                bfr[nt][1] = __float_as_uint(bp[4]);
            }
            #pragma unroll
            for (int mt = 0; mt < 4; mt++)
                #pragma unroll
                for (int nt = 0; nt < 8; nt++)
                    mma_tf32(acc[mt][nt], afr[mt], bfr[nt]);
        }

        if (it + 2 < 32) load_chunk(it + 2, (it + 2) % 3);
    }

    const int mBase = m0 + wm * 64;
    const int nBase = n0 + wn * 64;
    #pragma unroll
    for (int mt = 0; mt < 4; mt++) {
        #pragma unroll
        for (int nt = 0; nt < 8; nt++) {
            const int r0 = mBase + mt * 16 + g;
            const int c  = nBase + nt * 8 + 2 * tg;
            float2 bv = *(const float2*)(bs + c);
            float s00 = 1.f / (1.f + expf(-(acc[mt][nt][0] + bv.x)));
            float s01 = 1.f / (1.f + expf(-(acc[mt][nt][1] + bv.y)));
            float s10 = 1.f / (1.f + expf(-(acc[mt][nt][2] + bv.x)));
            float s11 = 1.f / (1.f + expf(-(acc[mt][nt][3] + bv.y)));
            *(__half2*)(g_selh + (size_t)r0 * 1024 + c)       = __floats2half2_rn(s00, s01);
            *(__half2*)(g_selh + (size_t)(r0 + 8) * 1024 + c) = __floats2half2_rn(s10, s11);
        }
    }
}

// ============================================================================
// Kernel B: class projections  g_c{a,b} = P @ W{a,b}^T + S*b{a,b} + b_emb[idx]
// ============================================================================
__global__ __launch_bounds__(256, 1) void k_cproj(
    const int* __restrict__ n_idx, const float* __restrict__ b_emb,
    const float* __restrict__ ba, const float* __restrict__ bb)
{
    extern __shared__ float sm[];

    const int n0 = blockIdx.x * 256;
    const int m0 = blockIdx.y * 128;
    const int side = blockIdx.z;
    const float* P    = side ? g_pb  : g_pa;
    const float* sums = side ? g_bfw : g_afw;
    const float* bias = side ? bb    : ba;
    float*       out  = side ? g_cb  : g_ca;
    const float* Wt = g_wtf + (size_t)(side ? 2 : 1) * ND * ND;

    const int tid = threadIdx.x;
    const int wid = tid >> 5, lane = tid & 31;
    const int wm = wid >> 2, wn = wid & 3;
    const int g = lane >> 2, tg = lane & 3;

    const uint32_t sb = smem_u32(sm);

    float acc[4][8][4];
    #pragma unroll
    for (int mt = 0; mt < 4; mt++)
        #pragma unroll
        for (int nt = 0; nt < 8; nt++)
            #pragma unroll
            for (int r = 0; r < 4; r++) acc[mt][nt][r] = 0.f;

    const int ldRow = tid >> 3;
    const int ldSeg = tid & 7;

    auto load_chunk = [&](int kc, int st) {
        const uint32_t s0 = sb + (uint32_t)(st * STG_F) * 4u;
        const uint32_t bB = s0 + (uint32_t)(128 * PADK) * 4u;
        const float* xs = P  + (size_t)m0 * 1024 + kc * 32;
        const float* ws = Wt + (size_t)n0 * 1024 + kc * 32;
        #pragma unroll
        for (int s = 0; s < 4; ++s) {
            int row = ldRow + s * 32;
            cp_async16(s0 + (uint32_t)(row * PADK + ldSeg * 4) * 4u,
                       xs + (size_t)row * 1024 + ldSeg * 4);
        }
        #pragma unroll
        for (int s = 0; s < 8; ++s) {
            int row = ldRow + s * 32;
            cp_async16(bB + (uint32_t)(row * PADK + ldSeg * 4) * 4u,
                       ws + (size_t)row * 1024 + ldSeg * 4);
        }
        asm volatile("cp.async.commit_group;" ::: "memory");
    };

    load_chunk(0, 0);
    load_chunk(1, 1);

    for (int it = 0; it < 32; ++it) {
        const int st = it % 3;
        if (it < 31) {
            asm volatile("cp.async.wait_group 1;" ::: "memory");
        } else {
            asm volatile("cp.async.wait_group 0;" ::: "memory");
        }
        __syncthreads();

        const float* As = sm + st * STG_F;
        const float* Bs = As + 128 * PADK;

        #pragma unroll
        for (int ks = 0; ks < 4; ++ks) {
            const int kb = ks * 8;
            uint32_t afr[4][4];
            #pragma unroll
            for (int mt = 0; mt < 4; mt++) {
                const float* ap = As + (wm * 64 + mt * 16 + g) * PADK + kb + tg;
                afr[mt][0] = __float_as_uint(ap[0]);
                afr[mt][1] = __float_as_uint(ap[8 * PADK]);
                afr[mt][2] = __float_as_uint(ap[4]);
                afr[mt][3] = __float_as_uint(ap[8 * PADK + 4]);
            }
            uint32_t bfr[8][2];
            #pragma unroll
            for (int nt = 0; nt < 8; nt++) {
                const float* bp = Bs + (wn * 64 + nt * 8 + g) * PADK + kb + tg;
                bfr[nt][0] = __float_as_uint(bp[0]);
                bfr[nt][1] = __float_as_uint(bp[4]);
            }
            #pragma unroll
            for (int mt = 0; mt < 4; mt++)
                #pragma unroll
                for (int nt = 0; nt < 8; nt++)
                    mma_tf32(acc[mt][nt], afr[mt], bfr[nt]);
        }

        if (it + 2 < 32) load_chunk(it + 2, (it + 2) % 3);
    }

    const int mBase = m0 + wm * 64;
    const int nBase = n0 + wn * 64;
    #pragma unroll
    for (int mt = 0; mt < 4; mt++) {
        const int r0 = mBase + mt * 16 + g;
        const int b  = r0 >> 6;
        const int e0 = r0 & 63;
        float s0v = sums[b * 64 + e0];
        float s1v = sums[b * 64 + e0 + 8];
        float S0 = s0v / (s0v + 1e-9f);
        float S1 = s1v / (s1v + 1e-9f);
        const float* br0 = b_emb + (size_t)n_idx[b * 64 + e0] * 1024;
        const float* br1 = b_emb + (size_t)n_idx[b * 64 + e0 + 8] * 1024;
        #pragma unroll
        for (int nt = 0; nt < 8; nt++) {
            const int c = nBase + nt * 8 + 2 * tg;
            float2 bv = *(const float2*)(bias + c);
            float2 e0v = *(const float2*)(br0 + c);
            float2 e1v = *(const float2*)(br1 + c);
            *(float2*)(out + (size_t)r0 * 1024 + c) = make_float2(
                rnd_tf32(acc[mt][nt][0] + S0 * bv.x + e0v.x),
                rnd_tf32(acc[mt][nt][1] + S0 * bv.y + e0v.y));
            *(float2*)(out + (size_t)(r0 + 8) * 1024 + c) = make_float2(
                rnd_tf32(acc[mt][nt][2] + S1 * bv.x + e1v.x),
                rnd_tf32(acc[mt][nt][3] + S1 * bv.y + e1v.y));
        }
    }
}

// ============================================================================
// Kernel C: qw = q_emb @ Wk  (M=64, N=1024, K=1024), B k-major. grid(8).
// ============================================================================
#define PADN 136
#define QW_STAGE_F (64 * PADK + 32 * PADN)
#define QW_SMEM_BYTES (2 * QW_STAGE_F * 4)

__global__ __launch_bounds__(256) void k_qw()
{
    extern __shared__ float sm[];
    const int n0 = blockIdx.x * 128;
    const float* Wt = g_wtf;

    const int tid = threadIdx.x;
    const int wid = tid >> 5, lane = tid & 31;
    const int wm = wid >> 2, wn = wid & 3;
    const int g = lane >> 2, tg = lane & 3;

    const uint32_t sb = smem_u32(sm);

    float acc[2][4][4];
    #pragma unroll
    for (int mt = 0; mt < 2; mt++)
        #pragma unroll
        for (int nt = 0; nt < 4; nt++)
            #pragma unroll
            for (int r = 0; r < 4; r++) acc[mt][nt][r] = 0.f;

    const int aRow = tid >> 3;
    const int aSeg = tid & 7;
    const int bRow = tid >> 5;
    const int bSeg = tid & 31;

    auto load_chunk = [&](int kc, int st) {
        const uint32_t s0 = sb + (uint32_t)(st * QW_STAGE_F) * 4u;
        const uint32_t bBase = s0 + (uint32_t)(64 * PADK) * 4u;
        const int kk = kc * 32;
        cp_async16(s0 + (uint32_t)(aRow * PADK + aSeg * 4) * 4u,
                   g_qtf + (size_t)aRow * 1024 + kk + aSeg * 4);
        cp_async16(s0 + (uint32_t)((aRow + 32) * PADK + aSeg * 4) * 4u,
                   g_qtf + (size_t)(aRow + 32) * 1024 + kk + aSeg * 4);
        const float* ws = Wt + (size_t)kk * 1024 + n0;
        #pragma unroll
        for (int s = 0; s < 4; ++s) {
            int row = bRow + s * 8;
            cp_async16(bBase + (uint32_t)(row * PADN + bSeg * 4) * 4u,
                       ws + (size_t)row * 1024 + bSeg * 4);
        }
        asm volatile("cp.async.commit_group;" ::: "memory");
    };

    load_chunk(0, 0);

    for (int it = 0; it < 32; ++it) {
        const int buf = it & 1;
        if (it + 1 < 32) {
            load_chunk(it + 1, buf ^ 1);
            asm volatile("cp.async.wait_group 1;" ::: "memory");
        } else {
            asm volatile("cp.async.wait_group 0;" ::: "memory");
        }
        __syncthreads();

        const float* As = sm + buf * QW_STAGE_F;
        const float* Bs = As + 64 * PADK;

        #pragma unroll
        for (int ks = 0; ks < 4; ++ks) {
            const int kb = ks * 8;
            uint32_t afr[2][4];
            #pragma unroll
            for (int mt = 0; mt < 2; mt++) {
                const float* ap = As + (wm * 32 + mt * 16 + g) * PADK + kb + tg;
                afr[mt][0] = __float_as_uint(ap[0]);
                afr[mt][1] = __float_as_uint(ap[8 * PADK]);
                afr[mt][2] = __float_as_uint(ap[4]);
                afr[mt][3] = __float_as_uint(ap[8 * PADK + 4]);
            }
            uint32_t bfr[4][2];
            #pragma unroll
            for (int nt = 0; nt < 4; nt++) {
                const float* bp = Bs + (kb + tg) * PADN + wn * 32 + nt * 8 + g;
                bfr[nt][0] = __float_as_uint(bp[0]);
                bfr[nt][1] = __float_as_uint(bp[4 * PADN]);
            }
            #pragma unroll
            for (int mt = 0; mt < 2; mt++)
                #pragma unroll
                for (int nt = 0; nt < 4; nt++)
                    mma_tf32(acc[mt][nt], afr[mt], bfr[nt]);
        }
        __syncthreads();
    }

    #pragma unroll
    for (int mt = 0; mt < 2; mt++) {
        const int e0 = wm * 32 + mt * 16 + g;
        #pragma unroll
        for (int nt = 0; nt < 4; nt++) {
            const int c = n0 + wn * 32 + nt * 8 + 2 * tg;
            *(float2*)(g_qw + (size_t)e0 * 1024 + c) =
                make_float2(rnd_tf32(acc[mt][nt][0]), rnd_tf32(acc[mt][nt][1]));
            *(float2*)(g_qw + (size_t)(e0 + 8) * 1024 + c) =
                make_float2(rnd_tf32(acc[mt][nt][2]), rnd_tf32(acc[mt][nt][3]));
        }
    }
}

// Kernel C2: qb[e] = q_emb[e] . bk
__global__ void k_qb(const float* __restrict__ q_emb, const float* __restrict__ bk)
{
    int e = threadIdx.x;
    if (e >= 64) return;
    float s = 0.f;
    const float* qr = q_emb + (size_t)e * 1024;
    for (int d = 0; d < 1024; ++d) s += qr[d] * bk[d];
    g_qb[e] = s;
}

// ============================================================================
// Kernel D: z[b,e,l] = (qw[idx[b,e]] . x[b,l] + qb[idx]) / 32
// ============================================================================
#define Z_STAGE_F (64 * PADK + 128 * PADK)
#define Z_SMEM_BYTES (2 * Z_STAGE_F * 4)

__global__ __launch_bounds__(256) void k_zgemm_mma(const int* __restrict__ n_idx)
{
    extern __shared__ float sm[];
    const int b  = blockIdx.y;
    const int l0 = blockIdx.x * 128;
    const int tid = threadIdx.x;
    const int wid = tid >> 5, lane = tid & 31;
    const int wm = wid >> 2, wn = wid & 3;
    const int g = lane >> 2, tg = lane & 3;

    const uint32_t sb = smem_u32(sm);

    float acc[2][4][4];
    #pragma unroll
    for (int mt = 0; mt < 2; mt++)
        #pragma unroll
        for (int nt = 0; nt < 4; nt++)
            #pragma unroll
            for (int r = 0; r < 4; r++) acc[mt][nt][r] = 0.f;

    const int aRow0 = tid >> 3;
    const int aSeg  = tid & 7;
    const float* aSrc0 = g_qw + (size_t)n_idx[b * 64 + aRow0] * 1024;
    const float* aSrc1 = g_qw + (size_t)n_idx[b * 64 + aRow0 + 32] * 1024;

    const int bRow = tid >> 3;
    const int bSeg = tid & 7;

    auto load_chunk = [&](int kc, int st) {
        const uint32_t s0 = sb + (uint32_t)(st * Z_STAGE_F) * 4u;
        const uint32_t bBase = s0 + (uint32_t)(64 * PADK) * 4u;
        cp_async16(s0 + (uint32_t)(aRow0 * PADK + aSeg * 4) * 4u, aSrc0 + kc * 32 + aSeg * 4);
        cp_async16(s0 + (uint32_t)((aRow0 + 32) * PADK + aSeg * 4) * 4u, aSrc1 + kc * 32 + aSeg * 4);
        const float* xs = g_xtf + ((size_t)b * 2048 + l0) * 1024 + kc * 32;
        #pragma unroll
        for (int s = 0; s < 4; ++s) {
            int row = bRow + s * 32;
            cp_async16(bBase + (uint32_t)(row * PADK + bSeg * 4) * 4u,
                       xs + (size_t)row * 1024 + bSeg * 4);
        }
        asm volatile("cp.async.commit_group;" ::: "memory");
    };

    load_chunk(0, 0);

    for (int it = 0; it < 32; ++it) {
        const int buf = it & 1;
        if (it + 1 < 32) {
            load_chunk(it + 1, buf ^ 1);
            asm volatile("cp.async.wait_group 1;" ::: "memory");
        } else {
            asm volatile("cp.async.wait_group 0;" ::: "memory");
        }
        __syncthreads();

        const float* As = sm + buf * Z_STAGE_F;
        const float* Bs = As + 64 * PADK;

        #pragma unroll
        for (int ks = 0; ks < 4; ++ks) {
            const int kb = ks * 8;
            uint32_t afr[2][4];
            #pragma unroll
            for (int mt = 0; mt < 2; mt++) {
                const float* ap = As + (wm * 32 + mt * 16 + g) * PADK + kb + tg;
                afr[mt][0] = __float_as_uint(ap[0]);
                afr[mt][1] = __float_as_uint(ap[8 * PADK]);
                afr[mt][2] = __float_as_uint(ap[4]);
                afr[mt][3] = __float_as_uint(ap[8 * PADK + 4]);
            }
            uint32_t bfr[4][2];
            #pragma unroll
            for (int nt = 0; nt < 4; nt++) {
                const float* bp = Bs + (wn * 32 + nt * 8 + g) * PADK + kb + tg;
                bfr[nt][0] = __float_as_uint(bp[0]);
                bfr[nt][1] = __float_as_uint(bp[4]);
            }
            #pragma unroll
            for (int mt = 0; mt < 2; mt++)
                #pragma unroll
                for (int nt = 0; nt < 4; nt++)
                    mma_tf32(acc[mt][nt], afr[mt], bfr[nt]);
        }
        __syncthreads();
    }

    #pragma unroll
    for (int mt = 0; mt < 2; mt++) {
        #pragma unroll
        for (int nt = 0; nt < 4; nt++) {
            const int e = wm * 32 + mt * 16 + g;
            const float qb0 = g_qb[n_idx[b * 64 + e]];
            const float qb1 = g_qb[n_idx[b * 64 + e + 8]];
            const int l = l0 + wn * 32 + nt * 8 + 2 * tg;
            float* zr0 = g_z + ((size_t)b * 64 + e) * 2048 + l;
            float* zr1 = g_z + ((size_t)b * 64 + e + 8) * 2048 + l;
            *(float2*)zr0 = make_float2((acc[mt][nt][0] + qb0) * 0.03125f,
                                        (acc[mt][nt][1] + qb0) * 0.03125f);
            *(float2*)zr1 = make_float2((acc[mt][nt][2] + qb1) * 0.03125f,
                                        (acc[mt][nt][3] + qb1) * 0.03125f);
        }
    }
}

// ============================================================================
// Kernel 3: forward (masked) sums over L for each (b,e)
// ============================================================================
__global__ __launch_bounds__(256) void k_fwsums(const int* __restrict__ mask)
{
    const int be = blockIdx.x;
    const int b = be >> 6;
    const float* zr = g_z + (size_t)be * 2048;
    const int* mrow = mask + b * 2048;

    float sa = 0.f, sb = 0.f;
    for (int l = threadIdx.x; l < 2048; l += 256) {
        float v = zr[l];
        if (mrow[l] != 0) { sa += fmaxf(v, 0.f); sb += fmaxf(-v, 0.f); }
    }
    #pragma unroll
    for (int off = 16; off > 0; off >>= 1) {
        sa += __shfl_down_sync(0xffffffffu, sa, off);
        sb += __shfl_down_sync(0xffffffffu, sb, off);
    }
    __shared__ float ra[8], rb[8];
    int wrp = threadIdx.x >> 5, lane = threadIdx.x & 31;
    if (lane == 0) { ra[wrp] = sa; rb[wrp] = sb; }
    __syncthreads();
    if (threadIdx.x == 0) {
        float ta = 0.f, tb = 0.f;
        #pragma unroll
        for (int i = 0; i < 8; i++) { ta += ra[i]; tb += rb[i]; }
        g_afw[be] = ta; g_bfw[be] = tb;
    }
}

// ============================================================================
// Kernel 4: backward (unmasked) sums over E for each (b,l)
// ============================================================================
__global__ __launch_bounds__(256) void k_bwsums()
{
    const int idx = blockIdx.x * 256 + threadIdx.x;
    const int b = idx >> 11;
    const float* zp = g_z + (size_t)b * 64 * 2048 + (idx & 2047);
    float sa = 0.f, sb = 0.f;
    #pragma unroll 8
    for (int e = 0; e < 64; e++) {
        float v = zp[(size_t)e * 2048];
        sa += fmaxf(v, 0.f);
        sb += fmaxf(-v, 0.f);
    }
    g_abw[idx] = sa;
    g_bbw[idx] = sb;
}

// ============================================================================
// Kernel E: merged P GEMM (both sides).  g_p{a,b}[b,e,d] = (A_{a,b} @ x)*inv
// M=64 (E), N=128 (d-block), K=2048 (l). One z read builds both A matrices;
// one x tile shared by both sides.
// ============================================================================
#define PG2_STAGE_F (2 * 64 * PADK + 32 * PADN)
#define PG2_SMEM_BYTES (2 * PG2_STAGE_F * 4)

__global__ __launch_bounds__(256) void k_pgemm2(const int* __restrict__ mask)
{
    extern __shared__ float sm[];
    const int b  = blockIdx.y;
    const int n0 = blockIdx.x * 128;

    const int tid = threadIdx.x;
    const int wid = tid >> 5, lane = tid & 31;
    const int wm = wid >> 2, wn = wid & 3;
    const int g = lane >> 2, tg = lane & 3;

    const uint32_t sb = smem_u32(sm);

    float accA[2][4][4], accB[2][4][4];
    #pragma unroll
    for (int mt = 0; mt < 2; mt++)
        #pragma unroll
        for (int nt = 0; nt < 4; nt++)
            #pragma unroll
            for (int r = 0; r < 4; r++) { accA[mt][nt][r] = 0.f; accB[mt][nt][r] = 0.f; }

    const int aE = tid >> 2;
    const int aC = (tid & 3) * 8;
    const float* zrow = g_z + ((size_t)b * 64 + aE) * 2048;
    const int* mrow = mask + b * 2048;

    const int bRow = tid >> 5;
    const int bSeg = tid & 31;

    auto load_chunk = [&](int kc, int st) {
        float* Aa = sm + st * PG2_STAGE_F;
        float* Ab = Aa + 64 * PADK;
        const uint32_t bBase = sb + (uint32_t)(st * PG2_STAGE_F + 2 * 64 * PADK) * 4u;
        const int kk = kc * 32;
        float4 v0 = *(const float4*)(zrow + kk + aC);
        float4 v1 = *(const float4*)(zrow + kk + aC + 4);
        int4 m0 = *(const int4*)(mrow + kk + aC);
        int4 m1 = *(const int4*)(mrow + kk + aC + 4);
        float* pa = Aa + aE * PADK + aC;
        float* pb = Ab + aE * PADK + aC;
        float vv[8] = { v0.x, v0.y, v0.z, v0.w, v1.x, v1.y, v1.z, v1.w };
        int   mm[8] = { m0.x, m0.y, m0.z, m0.w, m1.x, m1.y, m1.z, m1.w };
        #pragma unroll
        for (int j = 0; j < 8; ++j) {
            pa[j] = rnd_tf32(mm[j] ? fmaxf(vv[j], 0.f) : 0.f);
            pb[j] = rnd_tf32(mm[j] ? fmaxf(-vv[j], 0.f) : 0.f);
        }
        const float* bs_ = g_xtf + ((size_t)b * 2048 + kk) * 1024 + n0;
        #pragma unroll
        for (int s = 0; s < 4; ++s) {
            int row = bRow + s * 8;
            cp_async16(bBase + (uint32_t)(row * PADN + bSeg * 4) * 4u,
                       bs_ + (size_t)row * 1024 + bSeg * 4);
        }
        asm volatile("cp.async.commit_group;" ::: "memory");
    };

    load_chunk(0, 0);

    for (int it = 0; it < 64; ++it) {
        const int buf = it & 1;
        if (it + 1 < 64) {
            load_chunk(it + 1, buf ^ 1);
            asm volatile("cp.async.wait_group 1;" ::: "memory");
        } else {
            asm volatile("cp.async.wait_group 0;" ::: "memory");
        }
        __syncthreads();

        const float* Aa = sm + buf * PG2_STAGE_F;
        const float* Ab = Aa + 64 * PADK;
        const float* Bs = Ab + 64 * PADK;

        #pragma unroll
        for (int ks = 0; ks < 4; ++ks) {
            const int kb = ks * 8;
            uint32_t afa[2][4], afb[2][4];
            #pragma unroll
            for (int mt = 0; mt < 2; mt++) {
                const float* pa = Aa + (wm * 32 + mt * 16 + g) * PADK + kb + tg;
                const float* pb = Ab + (wm * 32 + mt * 16 + g) * PADK + kb + tg;
                afa[mt][0] = __float_as_uint(pa[0]);
                afa[mt][1] = __float_as_uint(pa[8 * PADK]);
                afa[mt][2] = __float_as_uint(pa[4]);
                afa[mt][3] = __float_as_uint(pa[8 * PADK + 4]);
                afb[mt][0] = __float_as_uint(pb[0]);
                afb[mt][1] = __float_as_uint(pb[8 * PADK]);
                afb[mt][2] = __float_as_uint(pb[4]);
                afb[mt][3] = __float_as_uint(pb[8 * PADK + 4]);
            }
            uint32_t bfr[4][2];
            #pragma unroll
            for (int nt = 0; nt < 4; nt++) {
                const float* bp = Bs + (kb + tg) * PADN + wn * 32 + nt * 8 + g;
                bfr[nt][0] = __float_as_uint(bp[0]);
                bfr[nt][1] = __float_as_uint(bp[4 * PADN]);
            }
            #pragma unroll
            for (int mt = 0; mt < 2; mt++)
                #pragma unroll
                for (int nt = 0; nt < 4; nt++) {
                    mma_tf32(accA[mt][nt], afa[mt], bfr[nt]);
                    mma_tf32(accB[mt][nt], afb[mt], bfr[nt]);
                }
        }
        __syncthreads();
    }

    #pragma unroll
    for (int mt = 0; mt < 2; mt++) {
        const int e0 = wm * 32 + mt * 16 + g;
        const float ia0 = 1.f / (g_afw[b * 64 + e0] + 1e-9f);
        const float ia1 = 1.f / (g_afw[b * 64 + e0 + 8] + 1e-9f);
        const float ib0 = 1.f / (g_bfw[b * 64 + e0] + 1e-9f);
        const float ib1 = 1.f / (g_bfw[b * 64 + e0 + 8] + 1e-9f);
        #pragma unroll
        for (int nt = 0; nt < 4; nt++) {
            const int d = n0 + wn * 32 + nt * 8 + 2 * tg;
            *(float2*)(g_pa + ((size_t)b * 64 + e0) * 1024 + d) = make_float2(
                rnd_tf32(accA[mt][nt][0] * ia0), rnd_tf32(accA[mt][nt][1] * ia0));
            *(float2*)(g_pa + ((size_t)b * 64 + e0 + 8) * 1024 + d) = make_float2(
                rnd_tf32(accA[mt][nt][2] * ia1), rnd_tf32(accA[mt][nt][3] * ia1));
            *(float2*)(g_pb + ((size_t)b * 64 + e0) * 1024 + d) = make_float2(
                rnd_tf32(accB[mt][nt][0] * ib0), rnd_tf32(accB[mt][nt][1] * ib0));
            *(float2*)(g_pb + ((size_t)b * 64 + e0 + 8) * 1024 + d) = make_float2(
                rnd_tf32(accB[mt][nt][2] * ib1), rnd_tf32(accB[mt][nt][3] * ib1));
        }
    }
}

// ============================================================================
// Kernel 6: final mix via tf32 mma.  M=64 (l), N=128 (d), K=64 (e).
// Reads pre-computed fp16 sigmoid selector.
// ============================================================================
#define PADK2 68
#define FN_SMEM_BYTES ((2 * 64 * PADK2 + 2 * 64 * PADN) * 4)

__global__ __launch_bounds__(256) void k_final_mma(float* __restrict__ out)
{
    extern __shared__ float sm[];
    float* Aa = sm;
    float* Ab = Aa + 64 * PADK2;
    float* Ba = Ab + 64 * PADK2;
    float* Bb = Ba + 64 * PADN;

    const int b  = blockIdx.z;
    const int l0 = blockIdx.y * 64;
    const int d0 = blockIdx.x * 128;
    const int tid = threadIdx.x;
    const int wid = tid >> 5, lane = tid & 31;
    const int wm = wid >> 2, wn = wid & 3;
    const int g = lane >> 2, tg = lane & 3;

    {
        const int e  = tid & 63;
        const int lc = (tid >> 6) * 16;
        const float* zp = g_z + ((size_t)b * 64 + e) * 2048 + l0 + lc;
        #pragma unroll
        for (int j = 0; j < 4; ++j) {
            float4 v = *(const float4*)(zp + j * 4);
            float vv[4] = { v.x, v.y, v.z, v.w };
            #pragma unroll
            for (int t = 0; t < 4; ++t) {
                int l = lc + j * 4 + t;
                Aa[l * PADK2 + e] = rnd_tf32(fmaxf(vv[t], 0.f));
                Ab[l * PADK2 + e] = rnd_tf32(fmaxf(-vv[t], 0.f));
            }
        }
    }
    {
        const uint32_t baU = smem_u32(Ba);
        const uint32_t bbU = smem_u32(Bb);
        const int row = tid >> 5, seg = tid & 31;
        const float* caP = g_ca + ((size_t)b * 64) * 1024 + d0;
        const float* cbP = g_cb + ((size_t)b * 64) * 1024 + d0;
        #pragma unroll
        for (int s = 0; s < 8; ++s) {
            int r = row + s * 8;
            uint32_t doff = (uint32_t)(r * PADN + seg * 4) * 4u;
            cp_async16(baU + doff, caP + (size_t)r * 1024 + seg * 4);
            cp_async16(bbU + doff, cbP + (size_t)r * 1024 + seg * 4);
        }
        asm volatile("cp.async.commit_group;" ::: "memory");
        asm volatile("cp.async.wait_group 0;" ::: "memory");
    }
    __syncthreads();

    float aca[2][4][4], acb[2][4][4];
    #pragma unroll
    for (int mt = 0; mt < 2; mt++)
        #pragma unroll
        for (int nt = 0; nt < 4; nt++)
            #pragma unroll
            for (int r = 0; r < 4; r++) { aca[mt][nt][r] = 0.f; acb[mt][nt][r] = 0.f; }

    #pragma unroll
    for (int ks = 0; ks < 8; ++ks) {
        const int kb = ks * 8;
        uint32_t afa[2][4], afb[2][4];
        #pragma unroll
        for (int mt = 0; mt < 2; mt++) {
            const float* pa = Aa + (wm * 32 + mt * 16 + g) * PADK2 + kb + tg;
            const float* pb = Ab + (wm * 32 + mt * 16 + g) * PADK2 + kb + tg;
            afa[mt][0] = __float_as_uint(pa[0]);
            afa[mt][1] = __float_as_uint(pa[8 * PADK2]);
            afa[mt][2] = __float_as_uint(pa[4]);
            afa[mt][3] = __float_as_uint(pa[8 * PADK2 + 4]);
            afb[mt][0] = __float_as_uint(pb[0]);
            afb[mt][1] = __float_as_uint(pb[8 * PADK2]);
            afb[mt][2] = __float_as_uint(pb[4]);
            afb[mt][3] = __float_as_uint(pb[8 * PADK2 + 4]);
        }
        uint32_t bfa[4][2], bfb[4][2];
        #pragma unroll
        for (int nt = 0; nt < 4; nt++) {
            const float* pa = Ba + (kb + tg) * PADN + wn * 32 + nt * 8 + g;
            const float* pb = Bb + (kb + tg) * PADN + wn * 32 + nt * 8 + g;
            bfa[nt][0] = __float_as_uint(pa[0]);
            bfa[nt][1] = __float_as_uint(pa[4 * PADN]);
            bfb[nt][0] = __float_as_uint(pb[0]);
            bfb[nt][1] = __float_as_uint(pb[4 * PADN]);
        }
        #pragma unroll
        for (int mt = 0; mt < 2; mt++)
            #pragma unroll
            for (int nt = 0; nt < 4; nt++) {
                mma_tf32(aca[mt][nt], afa[mt], bfa[nt]);
                mma_tf32(acb[mt][nt], afb[mt], bfb[nt]);
            }
    }

    #pragma unroll
    for (int mt = 0; mt < 2; mt++) {
        const int l0r = l0 + wm * 32 + mt * 16 + g;
        const float ia0 = 1.f / (g_abw[b * 2048 + l0r] + 1e-9f);
        const float ib0 = 1.f / (g_bbw[b * 2048 + l0r] + 1e-9f);
        const float ia1 = 1.f / (g_abw[b * 2048 + l0r + 8] + 1e-9f);
        const float ib1 = 1.f / (g_bbw[b * 2048 + l0r + 8] + 1e-9f);
        #pragma unroll
        for (int nt = 0; nt < 4; nt++) {
            const int d = d0 + wn * 32 + nt * 8 + 2 * tg;
            float2 sg0 = __half22float2(*(const __half2*)(g_selh + ((size_t)b * 2048 + l0r) * 1024 + d));
            float2 sg1 = __half22float2(*(const __half2*)(g_selh + ((size_t)b * 2048 + l0r + 8) * 1024 + d));
            float2 o0 = make_float2(
                sg0.x * (aca[mt][nt][0] * ia0) + (1.f - sg0.x) * (acb[mt][nt][0] * ib0),
                sg0.y * (aca[mt][nt][1] * ia0) + (1.f - sg0.y) * (acb[mt][nt][1] * ib0));
            float2 o1 = make_float2(
                sg1.x * (aca[mt][nt][2] * ia1) + (1.f - sg1.x) * (acb[mt][nt][2] * ib1),
                sg1.y * (aca[mt][nt][3] * ia1) + (1.f - sg1.y) * (acb[mt][nt][3] * ib1));
            *(float2*)(out + ((size_t)b * 2048 + l0r) * 1024 + d)     = o0;
            *(float2*)(out + ((size_t)b * 2048 + l0r + 8) * 1024 + d) = o1;
        }
    }
}

// ============================================================================
extern "C" void kernel_launch(void* const* d_in, const int* in_sizes, int n_in,
                              void* d_out, int out_size)
{
    const float* x     = (const float*)d_in[0];
    const int*   n_idx = (const int*)  d_in[1];
    const int*   mask  = (const int*)  d_in[2];
    const float* q_emb = (const float*)d_in[3];
    const float* b_emb = (const float*)d_in[4];
    const float* Wk    = (const float*)d_in[5];
    const float* bk    = (const float*)d_in[6];
    const float* Wa    = (const float*)d_in[7];
    const float* ba    = (const float*)d_in[8];
    const float* Wb    = (const float*)d_in[9];
    const float* bb    = (const float*)d_in[10];
    const float* Ws    = (const float*)d_in[11];
    const float* bs    = (const float*)d_in[12];
    float* out = (float*)d_out;

    float *xtf_p, *qtf_p;
    cudaGetSymbolAddress((void**)&xtf_p, g_xtf);
    cudaGetSymbolAddress((void**)&qtf_p, g_qtf);

    cudaFuncSetAttribute(k_selgemm, cudaFuncAttributeMaxDynamicSharedMemorySize, GM_SMEM_BYTES);
    cudaFuncSetAttribute(k_cproj, cudaFuncAttributeMaxDynamicSharedMemorySize, GM_SMEM_BYTES);
    cudaFuncSetAttribute(k_qw, cudaFuncAttributeMaxDynamicSharedMemorySize, QW_SMEM_BYTES);
    cudaFuncSetAttribute(k_zgemm_mma, cudaFuncAttributeMaxDynamicSharedMemorySize, Z_SMEM_BYTES);
    cudaFuncSetAttribute(k_pgemm2, cudaFuncAttributeMaxDynamicSharedMemorySize, PG2_SMEM_BYTES);
    cudaFuncSetAttribute(k_final_mma, cudaFuncAttributeMaxDynamicSharedMemorySize, FN_SMEM_BYTES);

    // tf32 rounding prepass (launches 0-2; selgemm = launch 5 for ncu -s 5)
    k_cvt <<<(NB * NL * ND / 4 + 255) / 256, 256>>>(x, xtf_p, NB * NL * ND / 4);
    k_cvt4<<<dim3(ND * ND / 4 / 256, 4),     256>>>(Wk, Wa, Wb, Ws);
    k_cvt <<<(NE * ND / 4 + 255) / 256,      256>>>(q_emb, qtf_p, NE * ND / 4);

    k_qw       <<<8,               256, QW_SMEM_BYTES>>>();
    k_qb       <<<1,               64>>>(q_emb, bk);
    k_selgemm  <<<dim3(4, 256),    256, GM_SMEM_BYTES>>>(bs);
    k_zgemm_mma<<<dim3(16, 16),    256, Z_SMEM_BYTES>>>(n_idx);
    k_fwsums   <<<NB * NE,         256>>>(mask);
    k_bwsums   <<<(NB * NL) / 256, 256>>>();
    k_pgemm2   <<<dim3(8, 16),     256, PG2_SMEM_BYTES>>>(mask);
    k_cproj    <<<dim3(4, 8, 2),   256, GM_SMEM_BYTES>>>(n_idx, b_emb, ba, bb);
    k_final_mma<<<dim3(8, 32, 16), 256, FN_SMEM_BYTES>>>(out);
}

// round 9
// speedup vs baseline: 1.4356x; 1.4356x over previous
#include <cuda_runtime.h>
#include <cuda_fp16.h>
#include <cstdint>
#include <math.h>

// Problem constants
#define NB 16
#define NL 2048
#define ND 1024
#define NE 64

// ---------------- scratch (device globals; no runtime allocation) ----------------
__device__ __half g_selh[(size_t)NB * NL * ND]; // sigmoid(x @ Ws^T + bs)
__device__ float  g_z   [(size_t)NB * NE * NL]; // attention logits (fp32)
__device__ __half g_pa  [(size_t)NB * NE * ND]; // normalized A_fw @ x
__device__ __half g_pb  [(size_t)NB * NE * ND];
__device__ __half g_ca  [(size_t)NB * NE * ND]; // class_a
__device__ __half g_cb  [(size_t)NB * NE * ND]; // class_b
__device__ float  g_afw [NB * NE];
__device__ float  g_bfw [NB * NE];
__device__ float  g_abw [NB * NL];
__device__ float  g_bbw [NB * NL];
__device__ __half g_xh  [(size_t)NB * NL * ND]; // x  (fp16)
__device__ __half g_wh  [(size_t)4 * ND * ND];  // Wk,Wa,Wb,Ws (fp16)
__device__ __half g_qh  [(size_t)NE * ND];      // q_emb (fp16)
__device__ __half g_qwh [(size_t)NE * ND];      // q_emb @ Wk (fp16)
__device__ float  g_qbv [NE];                   // q_emb . bk

// pads (in halves)
#define PADH  72    // [m/n][k] rows, BK=64 halves
#define PADH2 40    // [m][k] rows, BK=32 halves
#define PADNH 136   // [k][n] rows, 128 n-halves

// ============================================================================
// helpers
// ============================================================================
__device__ __forceinline__ uint32_t smem_u32(const void* p) {
    uint32_t a;
    asm("{ .reg .u64 t; cvta.to.shared.u64 t, %1; cvt.u32.u64 %0, t; }"
        : "=r"(a) : "l"(p));
    return a;
}

__device__ __forceinline__ void cp_async16(uint32_t dst, const void* src) {
    asm volatile("cp.async.cg.shared.global [%0], [%1], 16;" :: "r"(dst), "l"(src));
}

__device__ __forceinline__ void mma_f16(float* d, const uint32_t* a, const uint32_t* b) {
    asm volatile(
        "mma.sync.aligned.m16n8k16.row.col.f32.f16.f16.f32 "
        "{%0,%1,%2,%3}, {%4,%5,%6,%7}, {%8,%9}, {%0,%1,%2,%3};\n"
        : "+f"(d[0]), "+f"(d[1]), "+f"(d[2]), "+f"(d[3])
        : "r"(a[0]), "r"(a[1]), "r"(a[2]), "r"(a[3]), "r"(b[0]), "r"(b[1]));
}

// dual 16-bit load for [k][n] smem layouts: {B[k][n], B[k+1][n]}
__device__ __forceinline__ uint32_t ldpair(const __half* base, int k, int n, int strideH) {
    uint16_t lo = *(const uint16_t*)(base + (size_t)k * strideH + n);
    uint16_t hi = *(const uint16_t*)(base + (size_t)(k + 1) * strideH + n);
    return (uint32_t)lo | ((uint32_t)hi << 16);
}

// ============================================================================
// Kernel 0: fp32 -> fp16 conversion prepass
// ============================================================================
__global__ __launch_bounds__(256) void k_cvt_h(const float* __restrict__ src,
                                               __half* __restrict__ dst, int n4)
{
    int i = blockIdx.x * 256 + threadIdx.x;
    if (i >= n4) return;
    float4 v = ((const float4*)src)[i];
    __half2 h0 = __floats2half2_rn(v.x, v.y);
    __half2 h1 = __floats2half2_rn(v.z, v.w);
    uint2 o = make_uint2(*(uint32_t*)&h0, *(uint32_t*)&h1);
    ((uint2*)dst)[i] = o;
}

__global__ __launch_bounds__(256) void k_cvt4_h(
    const float* __restrict__ w0, const float* __restrict__ w1,
    const float* __restrict__ w2, const float* __restrict__ w3)
{
    const float* srcs[4] = { w0, w1, w2, w3 };
    const float* src = srcs[blockIdx.y];
    __half* dst = g_wh + (size_t)blockIdx.y * ND * ND;
    int i = blockIdx.x * 256 + threadIdx.x;
    float4 v = ((const float4*)src)[i];
    __half2 h0 = __floats2half2_rn(v.x, v.y);
    __half2 h1 = __floats2half2_rn(v.z, v.w);
    ((uint2*)dst)[i] = make_uint2(*(uint32_t*)&h0, *(uint32_t*)&h1);
}

// ============================================================================
// Kernel A: selector GEMM + sigmoid.  g_selh = sigmoid(x @ Ws^T + bs)
// fp16 mma. CTA 128x256, 8 warps 64x64, BK=64 halves, 3-stage ring.
// ============================================================================
#define SG_STG_H ((128 + 256) * PADH)
#define SG_SMEM (3 * SG_STG_H * 2)

__global__ __launch_bounds__(256, 1) void k_selgemm(const float* __restrict__ bs)
{
    extern __shared__ __half smh[];

    const int n0 = blockIdx.x * 256;
    const int m0 = blockIdx.y * 128;
    const __half* Wt = g_wh + (size_t)3 * ND * ND;

    const int tid = threadIdx.x;
    const int wid = tid >> 5, lane = tid & 31;
    const int wm = wid >> 2, wn = wid & 3;
    const int g = lane >> 2, tg = lane & 3;

    const uint32_t sb = smem_u32(smh);

    float acc[4][8][4];
    #pragma unroll
    for (int mt = 0; mt < 4; mt++)
        #pragma unroll
        for (int nt = 0; nt < 8; nt++)
            #pragma unroll
            for (int r = 0; r < 4; r++) acc[mt][nt][r] = 0.f;

    const int ldRow = tid >> 3;
    const int ldSeg = tid & 7;

    auto load_chunk = [&](int kc, int st) {
        const uint32_t s0 = sb + (uint32_t)(st * SG_STG_H) * 2u;
        const uint32_t bB = s0 + (uint32_t)(128 * PADH) * 2u;
        const __half* xs = g_xh + (size_t)m0 * 1024 + kc * 64;
        const __half* ws = Wt   + (size_t)n0 * 1024 + kc * 64;
        #pragma unroll
        for (int s = 0; s < 4; ++s) {
            int row = ldRow + s * 32;
            cp_async16(s0 + (uint32_t)(row * (PADH * 2) + ldSeg * 16),
                       xs + (size_t)row * 1024 + ldSeg * 8);
        }
        #pragma unroll
        for (int s = 0; s < 8; ++s) {
            int row = ldRow + s * 32;
            cp_async16(bB + (uint32_t)(row * (PADH * 2) + ldSeg * 16),
                       ws + (size_t)row * 1024 + ldSeg * 8);
        }
        asm volatile("cp.async.commit_group;" ::: "memory");
    };

    load_chunk(0, 0);
    load_chunk(1, 1);

    for (int it = 0; it < 16; ++it) {
        const int st = it % 3;
        if (it < 15) {
            asm volatile("cp.async.wait_group 1;" ::: "memory");
        } else {
            asm volatile("cp.async.wait_group 0;" ::: "memory");
        }
        __syncthreads();

        const __half* As = smh + st * SG_STG_H;
        const __half* Bs = As + 128 * PADH;

        #pragma unroll
        for (int ks = 0; ks < 4; ++ks) {
            const int kb = ks * 16;
            uint32_t afr[4][4];
            #pragma unroll
            for (int mt = 0; mt < 4; mt++) {
                const __half* ap = As + (wm * 64 + mt * 16 + g) * PADH + kb + 2 * tg;
                afr[mt][0] = *(const uint32_t*)ap;
                afr[mt][1] = *(const uint32_t*)(ap + 8 * PADH);
                afr[mt][2] = *(const uint32_t*)(ap + 8);
                afr[mt][3] = *(const uint32_t*)(ap + 8 * PADH + 8);
            }
            uint32_t bfr[8][2];
            #pragma unroll
            for (int nt = 0; nt < 8; nt++) {
                const __half* bp = Bs + (wn * 64 + nt * 8 + g) * PADH + kb + 2 * tg;
                bfr[nt][0] = *(const uint32_t*)bp;
                bfr[nt][1] = *(const uint32_t*)(bp + 8);
            }
            #pragma unroll
            for (int mt = 0; mt < 4; mt++)
                #pragma unroll
                for (int nt = 0; nt < 8; nt++)
                    mma_f16(acc[mt][nt], afr[mt], bfr[nt]);
        }

        if (it + 2 < 16) load_chunk(it + 2, (it + 2) % 3);
    }

    const int mBase = m0 + wm * 64;
    const int nBase = n0 + wn * 64;
    #pragma unroll
    for (int mt = 0; mt < 4; mt++) {
        #pragma unroll
        for (int nt = 0; nt < 8; nt++) {
            const int r0 = mBase + mt * 16 + g;
            const int c  = nBase + nt * 8 + 2 * tg;
            float2 bv = *(const float2*)(bs + c);
            float s00 = 1.f / (1.f + expf(-(acc[mt][nt][0] + bv.x)));
            float s01 = 1.f / (1.f + expf(-(acc[mt][nt][1] + bv.y)));
            float s10 = 1.f / (1.f + expf(-(acc[mt][nt][2] + bv.x)));
            float s11 = 1.f / (1.f + expf(-(acc[mt][nt][3] + bv.y)));
            *(__half2*)(g_selh + (size_t)r0 * 1024 + c)       = __floats2half2_rn(s00, s01);
            *(__half2*)(g_selh + (size_t)(r0 + 8) * 1024 + c) = __floats2half2_rn(s10, s11);
        }
    }
}

// ============================================================================
// Kernel B: class projections  g_c{a,b} = P @ W{a,b}^T + S*b{a,b} + b_emb[idx]
// fp16 mma, same geometry as selgemm. grid (4, 8, 2).
// ============================================================================
__global__ __launch_bounds__(256, 1) void k_cproj(
    const int* __restrict__ n_idx, const float* __restrict__ b_emb,
    const float* __restrict__ ba, const float* __restrict__ bb)
{
    extern __shared__ __half smh[];

    const int n0 = blockIdx.x * 256;
    const int m0 = blockIdx.y * 128;
    const int side = blockIdx.z;
    const __half* P   = side ? g_pb  : g_pa;
    const float* sums = side ? g_bfw : g_afw;
    const float* bias = side ? bb    : ba;
    __half*      out  = side ? g_cb  : g_ca;
    const __half* Wt  = g_wh + (size_t)(side ? 2 : 1) * ND * ND;

    const int tid = threadIdx.x;
    const int wid = tid >> 5, lane = tid & 31;
    const int wm = wid >> 2, wn = wid & 3;
    const int g = lane >> 2, tg = lane & 3;

    const uint32_t sb = smem_u32(smh);

    float acc[4][8][4];
    #pragma unroll
    for (int mt = 0; mt < 4; mt++)
        #pragma unroll
        for (int nt = 0; nt < 8; nt++)
            #pragma unroll
            for (int r = 0; r < 4; r++) acc[mt][nt][r] = 0.f;

    const int ldRow = tid >> 3;
    const int ldSeg = tid & 7;

    auto load_chunk = [&](int kc, int st) {
        const uint32_t s0 = sb + (uint32_t)(st * SG_STG_H) * 2u;
        const uint32_t bB = s0 + (uint32_t)(128 * PADH) * 2u;
        const __half* xs = P  + (size_t)m0 * 1024 + kc * 64;
        const __half* ws = Wt + (size_t)n0 * 1024 + kc * 64;
        #pragma unroll
        for (int s = 0; s < 4; ++s) {
            int row = ldRow + s * 32;
            cp_async16(s0 + (uint32_t)(row * (PADH * 2) + ldSeg * 16),
                       xs + (size_t)row * 1024 + ldSeg * 8);
        }
        #pragma unroll
        for (int s = 0; s < 8; ++s) {
            int row = ldRow + s * 32;
            cp_async16(bB + (uint32_t)(row * (PADH * 2) + ldSeg * 16),
                       ws + (size_t)row * 1024 + ldSeg * 8);
        }
        asm volatile("cp.async.commit_group;" ::: "memory");
    };

    load_chunk(0, 0);
    load_chunk(1, 1);

    for (int it = 0; it < 16; ++it) {
        const int st = it % 3;
        if (it < 15) {
            asm volatile("cp.async.wait_group 1;" ::: "memory");
        } else {
            asm volatile("cp.async.wait_group 0;" ::: "memory");
        }
        __syncthreads();

        const __half* As = smh + st * SG_STG_H;
        const __half* Bs = As + 128 * PADH;

        #pragma unroll
        for (int ks = 0; ks < 4; ++ks) {
            const int kb = ks * 16;
            uint32_t afr[4][4];
            #pragma unroll
            for (int mt = 0; mt < 4; mt++) {
                const __half* ap = As + (wm * 64 + mt * 16 + g) * PADH + kb + 2 * tg;
                afr[mt][0] = *(const uint32_t*)ap;
                afr[mt][1] = *(const uint32_t*)(ap + 8 * PADH);
                afr[mt][2] = *(const uint32_t*)(ap + 8);
                afr[mt][3] = *(const uint32_t*)(ap + 8 * PADH + 8);
            }
            uint32_t bfr[8][2];
            #pragma unroll
            for (int nt = 0; nt < 8; nt++) {
                const __half* bp = Bs + (wn * 64 + nt * 8 + g) * PADH + kb + 2 * tg;
                bfr[nt][0] = *(const uint32_t*)bp;
                bfr[nt][1] = *(const uint32_t*)(bp + 8);
            }
            #pragma unroll
            for (int mt = 0; mt < 4; mt++)
                #pragma unroll
                for (int nt = 0; nt < 8; nt++)
                    mma_f16(acc[mt][nt], afr[mt], bfr[nt]);
        }

        if (it + 2 < 16) load_chunk(it + 2, (it + 2) % 3);
    }

    const int mBase = m0 + wm * 64;
    const int nBase = n0 + wn * 64;
    #pragma unroll
    for (int mt = 0; mt < 4; mt++) {
        const int r0 = mBase + mt * 16 + g;
        const int b  = r0 >> 6;
        const int e0 = r0 & 63;
        float s0v = sums[b * 64 + e0];
        float s1v = sums[b * 64 + e0 + 8];
        float S0 = s0v / (s0v + 1e-9f);
        float S1 = s1v / (s1v + 1e-9f);
        const float* br0 = b_emb + (size_t)n_idx[b * 64 + e0] * 1024;
        const float* br1 = b_emb + (size_t)n_idx[b * 64 + e0 + 8] * 1024;
        #pragma unroll
        for (int nt = 0; nt < 8; nt++) {
            const int c = nBase + nt * 8 + 2 * tg;
            float2 bv = *(const float2*)(bias + c);
            float2 e0v = *(const float2*)(br0 + c);
            float2 e1v = *(const float2*)(br1 + c);
            *(__half2*)(out + (size_t)r0 * 1024 + c) = __floats2half2_rn(
                acc[mt][nt][0] + S0 * bv.x + e0v.x,
                acc[mt][nt][1] + S0 * bv.y + e0v.y);
            *(__half2*)(out + (size_t)(r0 + 8) * 1024 + c) = __floats2half2_rn(
                acc[mt][nt][2] + S1 * bv.x + e1v.x,
                acc[mt][nt][3] + S1 * bv.y + e1v.y);
        }
    }
}

// ============================================================================
// Kernel C: qw = q_emb @ Wk  (M=64(e), N=1024(d), K=1024(j)). B=[k][n]. grid(8).
// ============================================================================
#define QW_STG_H (64 * PADH + 64 * PADNH)
#define QW_SMEM (2 * QW_STG_H * 2)

__global__ __launch_bounds__(256) void k_qw()
{
    extern __shared__ __half smh[];
    const int n0 = blockIdx.x * 128;

    const int tid = threadIdx.x;
    const int wid = tid >> 5, lane = tid & 31;
    const int wm = wid >> 2, wn = wid & 3;
    const int g = lane >> 2, tg = lane & 3;

    const uint32_t sb = smem_u32(smh);

    float acc[2][4][4];
    #pragma unroll
    for (int mt = 0; mt < 2; mt++)
        #pragma unroll
        for (int nt = 0; nt < 4; nt++)
            #pragma unroll
            for (int r = 0; r < 4; r++) acc[mt][nt][r] = 0.f;

    const int aRow = tid >> 3;
    const int aSeg = tid & 7;

    auto load_chunk = [&](int kc, int st) {
        const uint32_t s0 = sb + (uint32_t)(st * QW_STG_H) * 2u;
        const uint32_t bB = s0 + (uint32_t)(64 * PADH) * 2u;
        cp_async16(s0 + (uint32_t)(aRow * (PADH * 2) + aSeg * 16),
                   g_qh + (size_t)aRow * 1024 + kc * 64 + aSeg * 8);
        cp_async16(s0 + (uint32_t)((aRow + 32) * (PADH * 2) + aSeg * 16),
                   g_qh + (size_t)(aRow + 32) * 1024 + kc * 64 + aSeg * 8);
        #pragma unroll
        for (int s = 0; s < 4; ++s) {
            int slot = tid + s * 256;
            int row = slot >> 4, seg = slot & 15;
            cp_async16(bB + (uint32_t)(row * (PADNH * 2) + seg * 16),
                       g_wh + (size_t)(kc * 64 + row) * 1024 + n0 + seg * 8);
        }
        asm volatile("cp.async.commit_group;" ::: "memory");
    };

    load_chunk(0, 0);

    for (int it = 0; it < 16; ++it) {
        const int buf = it & 1;
        if (it + 1 < 16) {
            load_chunk(it + 1, buf ^ 1);
            asm volatile("cp.async.wait_group 1;" ::: "memory");
        } else {
            asm volatile("cp.async.wait_group 0;" ::: "memory");
        }
        __syncthreads();

        const __half* As = smh + buf * QW_STG_H;
        const __half* Bs = As + 64 * PADH;

        #pragma unroll
        for (int ks = 0; ks < 4; ++ks) {
            const int kb = ks * 16;
            uint32_t afr[2][4];
            #pragma unroll
            for (int mt = 0; mt < 2; mt++) {
                const __half* ap = As + (wm * 32 + mt * 16 + g) * PADH + kb + 2 * tg;
                afr[mt][0] = *(const uint32_t*)ap;
                afr[mt][1] = *(const uint32_t*)(ap + 8 * PADH);
                afr[mt][2] = *(const uint32_t*)(ap + 8);
                afr[mt][3] = *(const uint32_t*)(ap + 8 * PADH + 8);
            }
            uint32_t bfr[4][2];
            #pragma unroll
            for (int nt = 0; nt < 4; nt++) {
                const int n = wn * 32 + nt * 8 + g;
                bfr[nt][0] = ldpair(Bs, kb + 2 * tg, n, PADNH);
                bfr[nt][1] = ldpair(Bs, kb + 2 * tg + 8, n, PADNH);
            }
            #pragma unroll
            for (int mt = 0; mt < 2; mt++)
                #pragma unroll
                for (int nt = 0; nt < 4; nt++)
                    mma_f16(acc[mt][nt], afr[mt], bfr[nt]);
        }
        __syncthreads();
    }

    #pragma unroll
    for (int mt = 0; mt < 2; mt++) {
        const int e0 = wm * 32 + mt * 16 + g;
        #pragma unroll
        for (int nt = 0; nt < 4; nt++) {
            const int c = n0 + wn * 32 + nt * 8 + 2 * tg;
            *(__half2*)(g_qwh + (size_t)e0 * 1024 + c) =
                __floats2half2_rn(acc[mt][nt][0], acc[mt][nt][1]);
            *(__half2*)(g_qwh + (size_t)(e0 + 8) * 1024 + c) =
                __floats2half2_rn(acc[mt][nt][2], acc[mt][nt][3]);
        }
    }
}

// Kernel C2: qb[e] = q_emb[e] . bk
__global__ void k_qb(const float* __restrict__ q_emb, const float* __restrict__ bk)
{
    int e = threadIdx.x;
    if (e >= 64) return;
    float s = 0.f;
    const float* qr = q_emb + (size_t)e * 1024;
    for (int d = 0; d < 1024; ++d) s += qr[d] * bk[d];
    g_qbv[e] = s;
}

// ============================================================================
// Kernel D: z[b,e,l] = (qwh[idx[b,e]] . xh[b,l] + qb[idx]) / 32
// M=64(e), N=128(l), K=1024(d). A=[m][k], B=x[n=l][k=d] native. BK=64.
// ============================================================================
#define Z_STG_H ((64 + 128) * PADH)
#define Z_SMEM (2 * Z_STG_H * 2)

__global__ __launch_bounds__(256) void k_zgemm(const int* __restrict__ n_idx)
{
    extern __shared__ __half smh[];
    const int b  = blockIdx.y;
    const int l0 = blockIdx.x * 128;
    const int tid = threadIdx.x;
    const int wid = tid >> 5, lane = tid & 31;
    const int wm = wid >> 2, wn = wid & 3;
    const int g = lane >> 2, tg = lane & 3;

    const uint32_t sb = smem_u32(smh);

    float acc[2][4][4];
    #pragma unroll
    for (int mt = 0; mt < 2; mt++)
        #pragma unroll
        for (int nt = 0; nt < 4; nt++)
            #pragma unroll
            for (int r = 0; r < 4; r++) acc[mt][nt][r] = 0.f;

    const int aRow = tid >> 3;
    const int aSeg = tid & 7;
    const __half* aSrc0 = g_qwh + (size_t)n_idx[b * 64 + aRow] * 1024;
    const __half* aSrc1 = g_qwh + (size_t)n_idx[b * 64 + aRow + 32] * 1024;

    auto load_chunk = [&](int kc, int st) {
        const uint32_t s0 = sb + (uint32_t)(st * Z_STG_H) * 2u;
        const uint32_t bB = s0 + (uint32_t)(64 * PADH) * 2u;
        cp_async16(s0 + (uint32_t)(aRow * (PADH * 2) + aSeg * 16), aSrc0 + kc * 64 + aSeg * 8);
        cp_async16(s0 + (uint32_t)((aRow + 32) * (PADH * 2) + aSeg * 16), aSrc1 + kc * 64 + aSeg * 8);
        const __half* xs = g_xh + ((size_t)b * 2048 + l0) * 1024 + kc * 64;
        #pragma unroll
        for (int s = 0; s < 4; ++s) {
            int row = aRow + s * 32;
            cp_async16(bB + (uint32_t)(row * (PADH * 2) + aSeg * 16),
                       xs + (size_t)row * 1024 + aSeg * 8);
        }
        asm volatile("cp.async.commit_group;" ::: "memory");
    };

    load_chunk(0, 0);

    for (int it = 0; it < 16; ++it) {
        const int buf = it & 1;
        if (it + 1 < 16) {
            load_chunk(it + 1, buf ^ 1);
            asm volatile("cp.async.wait_group 1;" ::: "memory");
        } else {
            asm volatile("cp.async.wait_group 0;" ::: "memory");
        }
        __syncthreads();

        const __half* As = smh + buf * Z_STG_H;
        const __half* Bs = As + 64 * PADH;

        #pragma unroll
        for (int ks = 0; ks < 4; ++ks) {
            const int kb = ks * 16;
            uint32_t afr[2][4];
            #pragma unroll
            for (int mt = 0; mt < 2; mt++) {
                const __half* ap = As + (wm * 32 + mt * 16 + g) * PADH + kb + 2 * tg;
                afr[mt][0] = *(const uint32_t*)ap;
                afr[mt][1] = *(const uint32_t*)(ap + 8 * PADH);
                afr[mt][2] = *(const uint32_t*)(ap + 8);
                afr[mt][3] = *(const uint32_t*)(ap + 8 * PADH + 8);
            }
            uint32_t bfr[4][2];
            #pragma unroll
            for (int nt = 0; nt < 4; nt++) {
                const __half* bp = Bs + (wn * 32 + nt * 8 + g) * PADH + kb + 2 * tg;
                bfr[nt][0] = *(const uint32_t*)bp;
                bfr[nt][1] = *(const uint32_t*)(bp + 8);
            }
            #pragma unroll
            for (int mt = 0; mt < 2; mt++)
                #pragma unroll
                for (int nt = 0; nt < 4; nt++)
                    mma_f16(acc[mt][nt], afr[mt], bfr[nt]);
        }
        __syncthreads();
    }

    #pragma unroll
    for (int mt = 0; mt < 2; mt++) {
        #pragma unroll
        for (int nt = 0; nt < 4; nt++) {
            const int e = wm * 32 + mt * 16 + g;
            const float qb0 = g_qbv[n_idx[b * 64 + e]];
            const float qb1 = g_qbv[n_idx[b * 64 + e + 8]];
            const int l = l0 + wn * 32 + nt * 8 + 2 * tg;
            float* zr0 = g_z + ((size_t)b * 64 + e) * 2048 + l;
            float* zr1 = g_z + ((size_t)b * 64 + e + 8) * 2048 + l;
            *(float2*)zr0 = make_float2((acc[mt][nt][0] + qb0) * 0.03125f,
                                        (acc[mt][nt][1] + qb0) * 0.03125f);
            *(float2*)zr1 = make_float2((acc[mt][nt][2] + qb1) * 0.03125f,
                                        (acc[mt][nt][3] + qb1) * 0.03125f);
        }
    }
}

// ============================================================================
// Kernel 3/4: reduction sums (unchanged)
// ============================================================================
__global__ __launch_bounds__(256) void k_fwsums(const int* __restrict__ mask)
{
    const int be = blockIdx.x;
    const int b = be >> 6;
    const float* zr = g_z + (size_t)be * 2048;
    const int* mrow = mask + b * 2048;

    float sa = 0.f, sb = 0.f;
    for (int l = threadIdx.x; l < 2048; l += 256) {
        float v = zr[l];
        if (mrow[l] != 0) { sa += fmaxf(v, 0.f); sb += fmaxf(-v, 0.f); }
    }
    #pragma unroll
    for (int off = 16; off > 0; off >>= 1) {
        sa += __shfl_down_sync(0xffffffffu, sa, off);
        sb += __shfl_down_sync(0xffffffffu, sb, off);
    }
    __shared__ float ra[8], rb[8];
    int wrp = threadIdx.x >> 5, lane = threadIdx.x & 31;
    if (lane == 0) { ra[wrp] = sa; rb[wrp] = sb; }
    __syncthreads();
    if (threadIdx.x == 0) {
        float ta = 0.f, tb = 0.f;
        #pragma unroll
        for (int i = 0; i < 8; i++) { ta += ra[i]; tb += rb[i]; }
        g_afw[be] = ta; g_bfw[be] = tb;
    }
}

__global__ __launch_bounds__(256) void k_bwsums()
{
    const int idx = blockIdx.x * 256 + threadIdx.x;
    const int b = idx >> 11;
    const float* zp = g_z + (size_t)b * 64 * 2048 + (idx & 2047);
    float sa = 0.f, sb = 0.f;
    #pragma unroll 8
    for (int e = 0; e < 64; e++) {
        float v = zp[(size_t)e * 2048];
        sa += fmaxf(v, 0.f);
        sb += fmaxf(-v, 0.f);
    }
    g_abw[idx] = sa;
    g_bbw[idx] = sb;
}

// ============================================================================
// Kernel E: merged P GEMM. g_p{a,b}[b,e,d] = (A_{a,b} @ x)*inv   (fp16)
// M=64(e), N=128(d), K=2048(l). A built from z; B = xh [k=l][n=d] (dual-16).
// ============================================================================
#define PG_STG_H (2 * 64 * PADH2 + 32 * PADNH)
#define PG_SMEM (2 * PG_STG_H * 2)

__global__ __launch_bounds__(256) void k_pgemm2(const int* __restrict__ mask)
{
    extern __shared__ __half smh[];
    const int b  = blockIdx.y;
    const int n0 = blockIdx.x * 128;

    const int tid = threadIdx.x;
    const int wid = tid >> 5, lane = tid & 31;
    const int wm = wid >> 2, wn = wid & 3;
    const int g = lane >> 2, tg = lane & 3;

    const uint32_t sb = smem_u32(smh);

    float accA[2][4][4], accB[2][4][4];
    #pragma unroll
    for (int mt = 0; mt < 2; mt++)
        #pragma unroll
        for (int nt = 0; nt < 4; nt++)
            #pragma unroll
            for (int r = 0; r < 4; r++) { accA[mt][nt][r] = 0.f; accB[mt][nt][r] = 0.f; }

    const int aE = tid >> 2;
    const int aC = (tid & 3) * 8;
    const float* zrow = g_z + ((size_t)b * 64 + aE) * 2048;
    const int* mrow = mask + b * 2048;

    auto load_chunk = [&](int kc, int st) {
        __half* Aa = smh + st * PG_STG_H;
        __half* Ab = Aa + 64 * PADH2;
        const uint32_t bB = sb + (uint32_t)(st * PG_STG_H + 2 * 64 * PADH2) * 2u;
        const int kk = kc * 32;
        float4 v0 = *(const float4*)(zrow + kk + aC);
        float4 v1 = *(const float4*)(zrow + kk + aC + 4);
        int4 m0 = *(const int4*)(mrow + kk + aC);
        int4 m1 = *(const int4*)(mrow + kk + aC + 4);
        float vv[8] = { v0.x, v0.y, v0.z, v0.w, v1.x, v1.y, v1.z, v1.w };
        int   mm[8] = { m0.x, m0.y, m0.z, m0.w, m1.x, m1.y, m1.z, m1.w };
        __half ha[8], hb[8];
        #pragma unroll
        for (int j = 0; j < 8; ++j) {
            ha[j] = __float2half_rn(mm[j] ? fmaxf(vv[j], 0.f) : 0.f);
            hb[j] = __float2half_rn(mm[j] ? fmaxf(-vv[j], 0.f) : 0.f);
        }
        *(uint4*)(Aa + aE * PADH2 + aC) = *(uint4*)ha;
        *(uint4*)(Ab + aE * PADH2 + aC) = *(uint4*)hb;
        const __half* xs = g_xh + ((size_t)b * 2048 + kk) * 1024 + n0;
        #pragma unroll
        for (int s = 0; s < 2; ++s) {
            int slot = tid + s * 256;
            int row = slot >> 4, seg = slot & 15;
            cp_async16(bB + (uint32_t)(row * (PADNH * 2) + seg * 16),
                       xs + (size_t)row * 1024 + seg * 8);
        }
        asm volatile("cp.async.commit_group;" ::: "memory");
    };

    load_chunk(0, 0);

    for (int it = 0; it < 64; ++it) {
        const int buf = it & 1;
        if (it + 1 < 64) {
            load_chunk(it + 1, buf ^ 1);
            asm volatile("cp.async.wait_group 1;" ::: "memory");
        } else {
            asm volatile("cp.async.wait_group 0;" ::: "memory");
        }
        __syncthreads();

        const __half* Aa = smh + buf * PG_STG_H;
        const __half* Ab = Aa + 64 * PADH2;
        const __half* Bs = Ab + 64 * PADH2;

        #pragma unroll
        for (int ks = 0; ks < 2; ++ks) {
            const int kb = ks * 16;
            uint32_t afa[2][4], afb[2][4];
            #pragma unroll
            for (int mt = 0; mt < 2; mt++) {
                const __half* pa = Aa + (wm * 32 + mt * 16 + g) * PADH2 + kb + 2 * tg;
                const __half* pb = Ab + (wm * 32 + mt * 16 + g) * PADH2 + kb + 2 * tg;
                afa[mt][0] = *(const uint32_t*)pa;
                afa[mt][1] = *(const uint32_t*)(pa + 8 * PADH2);
                afa[mt][2] = *(const uint32_t*)(pa + 8);
                afa[mt][3] = *(const uint32_t*)(pa + 8 * PADH2 + 8);
                afb[mt][0] = *(const uint32_t*)pb;
                afb[mt][1] = *(const uint32_t*)(pb + 8 * PADH2);
                afb[mt][2] = *(const uint32_t*)(pb + 8);
                afb[mt][3] = *(const uint32_t*)(pb + 8 * PADH2 + 8);
            }
            uint32_t bfr[4][2];
            #pragma unroll
            for (int nt = 0; nt < 4; nt++) {
                const int n = wn * 32 + nt * 8 + g;
                bfr[nt][0] = ldpair(Bs, kb + 2 * tg, n, PADNH);
                bfr[nt][1] = ldpair(Bs, kb + 2 * tg + 8, n, PADNH);
            }
            #pragma unroll
            for (int mt = 0; mt < 2; mt++)
                #pragma unroll
                for (int nt = 0; nt < 4; nt++) {
                    mma_f16(accA[mt][nt], afa[mt], bfr[nt]);
                    mma_f16(accB[mt][nt], afb[mt], bfr[nt]);
                }
        }
        __syncthreads();
    }

    #pragma unroll
    for (int mt = 0; mt < 2; mt++) {
        const int e0 = wm * 32 + mt * 16 + g;
        const float ia0 = 1.f / (g_afw[b * 64 + e0] + 1e-9f);
        const float ia1 = 1.f / (g_afw[b * 64 + e0 + 8] + 1e-9f);
        const float ib0 = 1.f / (g_bfw[b * 64 + e0] + 1e-9f);
        const float ib1 = 1.f / (g_bfw[b * 64 + e0 + 8] + 1e-9f);
        #pragma unroll
        for (int nt = 0; nt < 4; nt++) {
            const int d = n0 + wn * 32 + nt * 8 + 2 * tg;
            *(__half2*)(g_pa + ((size_t)b * 64 + e0) * 1024 + d) =
                __floats2half2_rn(accA[mt][nt][0] * ia0, accA[mt][nt][1] * ia0);
            *(__half2*)(g_pa + ((size_t)b * 64 + e0 + 8) * 1024 + d) =
                __floats2half2_rn(accA[mt][nt][2] * ia1, accA[mt][nt][3] * ia1);
            *(__half2*)(g_pb + ((size_t)b * 64 + e0) * 1024 + d) =
                __floats2half2_rn(accB[mt][nt][0] * ib0, accB[mt][nt][1] * ib0);
            *(__half2*)(g_pb + ((size_t)b * 64 + e0 + 8) * 1024 + d) =
                __floats2half2_rn(accB[mt][nt][2] * ib1, accB[mt][nt][3] * ib1);
        }
    }
}

// ============================================================================
// Kernel 6: final mix (fp16 mma). M=64(l), N=128(d), K=64(e). Single shot.
// B = g_c{a,b} [k=e][n=d] (dual-16).
// ============================================================================
#define FN_SMEM ((2 * 64 * PADH + 2 * 64 * PADNH) * 2)

__global__ __launch_bounds__(256) void k_final(float* __restrict__ out)
{
    extern __shared__ __half smh[];
    __half* Aa = smh;
    __half* Ab = Aa + 64 * PADH;
    __half* Ba = Ab + 64 * PADH;
    __half* Bb = Ba + 64 * PADNH;

    const int b  = blockIdx.z;
    const int l0 = blockIdx.y * 64;
    const int d0 = blockIdx.x * 128;
    const int tid = threadIdx.x;
    const int wid = tid >> 5, lane = tid & 31;
    const int wm = wid >> 2, wn = wid & 3;
    const int g = lane >> 2, tg = lane & 3;

    {
        const int e  = tid & 63;
        const int lc = (tid >> 6) * 16;
        const float* zp = g_z + ((size_t)b * 64 + e) * 2048 + l0 + lc;
        #pragma unroll
        for (int j = 0; j < 4; ++j) {
            float4 v = *(const float4*)(zp + j * 4);
            float vv[4] = { v.x, v.y, v.z, v.w };
            #pragma unroll
            for (int t = 0; t < 4; ++t) {
                int l = lc + j * 4 + t;
                Aa[l * PADH + e] = __float2half_rn(fmaxf(vv[t], 0.f));
                Ab[l * PADH + e] = __float2half_rn(fmaxf(-vv[t], 0.f));
            }
        }
    }
    {
        const uint32_t baU = smem_u32(Ba);
        const uint32_t bbU = smem_u32(Bb);
        const __half* caP = g_ca + ((size_t)b * 64) * 1024 + d0;
        const __half* cbP = g_cb + ((size_t)b * 64) * 1024 + d0;
        #pragma unroll
        for (int s = 0; s < 4; ++s) {
            int slot = tid + s * 256;
            int row = slot >> 4, seg = slot & 15;
            uint32_t doff = (uint32_t)(row * (PADNH * 2) + seg * 16);
            cp_async16(baU + doff, caP + (size_t)row * 1024 + seg * 8);
            cp_async16(bbU + doff, cbP + (size_t)row * 1024 + seg * 8);
        }
        asm volatile("cp.async.commit_group;" ::: "memory");
        asm volatile("cp.async.wait_group 0;" ::: "memory");
    }
    __syncthreads();

    float aca[2][4][4], acb[2][4][4];
    #pragma unroll
    for (int mt = 0; mt < 2; mt++)
        #pragma unroll
        for (int nt = 0; nt < 4; nt++)
            #pragma unroll
            for (int r = 0; r < 4; r++) { aca[mt][nt][r] = 0.f; acb[mt][nt][r] = 0.f; }

    #pragma unroll
    for (int ks = 0; ks < 4; ++ks) {
        const int kb = ks * 16;
        uint32_t afa[2][4], afb[2][4];
        #pragma unroll
        for (int mt = 0; mt < 2; mt++) {
            const __half* pa = Aa + (wm * 32 + mt * 16 + g) * PADH + kb + 2 * tg;
            const __half* pb = Ab + (wm * 32 + mt * 16 + g) * PADH + kb + 2 * tg;
            afa[mt][0] = *(const uint32_t*)pa;
            afa[mt][1] = *(const uint32_t*)(pa + 8 * PADH);
            afa[mt][2] = *(const uint32_t*)(pa + 8);
            afa[mt][3] = *(const uint32_t*)(pa + 8 * PADH + 8);
            afb[mt][0] = *(const uint32_t*)pb;
            afb[mt][1] = *(const uint32_t*)(pb + 8 * PADH);
            afb[mt][2] = *(const uint32_t*)(pb + 8);
            afb[mt][3] = *(const uint32_t*)(pb + 8 * PADH + 8);
        }
        uint32_t bfa[4][2], bfb[4][2];
        #pragma unroll
        for (int nt = 0; nt < 4; nt++) {
            const int n = wn * 32 + nt * 8 + g;
            bfa[nt][0] = ldpair(Ba, kb + 2 * tg, n, PADNH);
            bfa[nt][1] = ldpair(Ba, kb + 2 * tg + 8, n, PADNH);
            bfb[nt][0] = ldpair(Bb, kb + 2 * tg, n, PADNH);
            bfb[nt][1] = ldpair(Bb, kb + 2 * tg + 8, n, PADNH);
        }
        #pragma unroll
        for (int mt = 0; mt < 2; mt++)
            #pragma unroll
            for (int nt = 0; nt < 4; nt++) {
                mma_f16(aca[mt][nt], afa[mt], bfa[nt]);
                mma_f16(acb[mt][nt], afb[mt], bfb[nt]);
            }
    }

    #pragma unroll
    for (int mt = 0; mt < 2; mt++) {
        const int l0r = l0 + wm * 32 + mt * 16 + g;
        const float ia0 = 1.f / (g_abw[b * 2048 + l0r] + 1e-9f);
        const float ib0 = 1.f / (g_bbw[b * 2048 + l0r] + 1e-9f);
        const float ia1 = 1.f / (g_abw[b * 2048 + l0r + 8] + 1e-9f);
        const float ib1 = 1.f / (g_bbw[b * 2048 + l0r + 8] + 1e-9f);
        #pragma unroll
        for (int nt = 0; nt < 4; nt++) {
            const int d = d0 + wn * 32 + nt * 8 + 2 * tg;
            float2 sg0 = __half22float2(*(const __half2*)(g_selh + ((size_t)b * 2048 + l0r) * 1024 + d));
            float2 sg1 = __half22float2(*(const __half2*)(g_selh + ((size_t)b * 2048 + l0r + 8) * 1024 + d));
            float2 o0 = make_float2(
                sg0.x * (aca[mt][nt][0] * ia0) + (1.f - sg0.x) * (acb[mt][nt][0] * ib0),
                sg0.y * (aca[mt][nt][1] * ia0) + (1.f - sg0.y) * (acb[mt][nt][1] * ib0));
            float2 o1 = make_float2(
                sg1.x * (aca[mt][nt][2] * ia1) + (1.f - sg1.x) * (acb[mt][nt][2] * ib1),
                sg1.y * (aca[mt][nt][3] * ia1) + (1.f - sg1.y) * (acb[mt][nt][3] * ib1));
            *(float2*)(out + ((size_t)b * 2048 + l0r) * 1024 + d)     = o0;
            *(float2*)(out + ((size_t)b * 2048 + l0r + 8) * 1024 + d) = o1;
        }
    }
}

// ============================================================================
extern "C" void kernel_launch(void* const* d_in, const int* in_sizes, int n_in,
                              void* d_out, int out_size)
{
    const float* x     = (const float*)d_in[0];
    const int*   n_idx = (const int*)  d_in[1];
    const int*   mask  = (const int*)  d_in[2];
    const float* q_emb = (const float*)d_in[3];
    const float* b_emb = (const float*)d_in[4];
    const float* bk    = (const float*)d_in[6];
    const float* Wa    = (const float*)d_in[7];
    const float* ba    = (const float*)d_in[8];
    const float* Wb    = (const float*)d_in[9];
    const float* bb    = (const float*)d_in[10];
    const float* Ws    = (const float*)d_in[11];
    const float* bs    = (const float*)d_in[12];
    const float* Wk    = (const float*)d_in[5];
    float* out = (float*)d_out;

    __half *xh_p, *qh_p;
    cudaGetSymbolAddress((void**)&xh_p, g_xh);
    cudaGetSymbolAddress((void**)&qh_p, g_qh);

    cudaFuncSetAttribute(k_selgemm, cudaFuncAttributeMaxDynamicSharedMemorySize, SG_SMEM);
    cudaFuncSetAttribute(k_cproj,   cudaFuncAttributeMaxDynamicSharedMemorySize, SG_SMEM);
    cudaFuncSetAttribute(k_qw,      cudaFuncAttributeMaxDynamicSharedMemorySize, QW_SMEM);
    cudaFuncSetAttribute(k_zgemm,   cudaFuncAttributeMaxDynamicSharedMemorySize, Z_SMEM);
    cudaFuncSetAttribute(k_pgemm2,  cudaFuncAttributeMaxDynamicSharedMemorySize, PG_SMEM);
    cudaFuncSetAttribute(k_final,   cudaFuncAttributeMaxDynamicSharedMemorySize, FN_SMEM);

    // fp16 prepass (launches 0-2; selgemm = launch 5 for ncu -s 5)
    k_cvt_h <<<(NB * NL * ND / 4 + 255) / 256, 256>>>(x, xh_p, NB * NL * ND / 4);
    k_cvt4_h<<<dim3(ND * ND / 4 / 256, 4),     256>>>(Wk, Wa, Wb, Ws);
    k_cvt_h <<<(NE * ND / 4 + 255) / 256,      256>>>(q_emb, qh_p, NE * ND / 4);

    k_qw     <<<8,               256, QW_SMEM>>>();
    k_qb     <<<1,               64>>>(q_emb, bk);
    k_selgemm<<<dim3(4, 256),    256, SG_SMEM>>>(bs);
    k_zgemm  <<<dim3(16, 16),    256, Z_SMEM>>>(n_idx);
    k_fwsums <<<NB * NE,         256>>>(mask);
    k_bwsums <<<(NB * NL) / 256, 256>>>();
    k_pgemm2 <<<dim3(8, 16),     256, PG_SMEM>>>(mask);
    k_cproj  <<<dim3(4, 8, 2),   256, SG_SMEM>>>(n_idx, b_emb, ba, bb);
    k_final  <<<dim3(8, 32, 16), 256, FN_SMEM>>>(out);
}